// round 2
// baseline (speedup 1.0000x reference)
#include <cuda_runtime.h>
#include <cstdint>
#include <cstring>

// ---------------------------------------------------------------------------
// GraphSAGE (2-layer, mean aggregator) + graph-mean readout + linear classifier
// Restructured: layer-2 is linear, so graph-mean(h2) = graph-mean(h1)@W2s +
// graph-mean(agg(h1))@W2n + b2.  The 100k-row layer-2 GEMM collapses to 64 rows,
// and agg(h1) is never materialized (SpMM2 accumulates straight into graph sums).
// ---------------------------------------------------------------------------

#define K_NODES  100000
#define K_EDGES  1600000
#define K_GRAPHS 64
#define K_DIM    128
#define K_CLS    8
#define K_NB     98            // ceil(100000/1024)

// scratch (static device memory; no allocations)
__device__ int   g_count [K_NODES];
__device__ int   g_rowptr[K_NODES + 1];
__device__ int   g_cursor[K_NODES];
__device__ int   g_esrc  [K_EDGES];
__device__ int   g_bsum  [128];
__device__ float g_gs1   [K_GRAPHS * K_DIM];   // per-graph sum of h1
__device__ float g_gs2   [K_GRAPHS * K_DIM];   // per-graph sum of agg(h1)
__device__ int   g_gcnt  [K_GRAPHS];
__device__ float g_hg    [K_GRAPHS * K_DIM];   // per-graph mean(h2)
__device__ float g_mean  [(size_t)K_NODES * K_DIM];
__device__ float g_h1    [(size_t)K_NODES * K_DIM];

// ---------------------------------------------------------------------------
// 0) zero the per-launch accumulators
__global__ void k_zero() {
    int i = blockIdx.x * blockDim.x + threadIdx.x;
    if (i < K_NODES)           g_count[i] = 0;
    if (i < K_GRAPHS * K_DIM) { g_gs1[i] = 0.0f; g_gs2[i] = 0.0f; }
    if (i < K_GRAPHS)          g_gcnt[i] = 0;
}

// 1) histogram of dst
__global__ void k_count(const int* __restrict__ dst) {
    int i = blockIdx.x * blockDim.x + threadIdx.x;
    if (i < K_EDGES) atomicAdd(&g_count[dst[i]], 1);
}

// 2a) per-1024-chunk sums
__global__ void k_reduce_chunks() {
    __shared__ int sm[256];
    int b = blockIdx.x, t = threadIdx.x;
    int base = b * 1024 + t * 4;
    int s = 0;
#pragma unroll
    for (int j = 0; j < 4; ++j) {
        int i = base + j;
        if (i < K_NODES) s += g_count[i];
    }
    sm[t] = s;
    __syncthreads();
    for (int o = 128; o > 0; o >>= 1) {
        if (t < o) sm[t] += sm[t + o];
        __syncthreads();
    }
    if (t == 0) g_bsum[b] = sm[0];
}

// 2b) scan the chunk sums (single block)
__global__ void k_scan_bsums() {
    __shared__ int sm[128];
    int t = threadIdx.x;
    int v = (t < K_NB) ? g_bsum[t] : 0;
    sm[t] = v;
    __syncthreads();
    for (int o = 1; o < 128; o <<= 1) {
        int u = (t >= o) ? sm[t - o] : 0;
        __syncthreads();
        sm[t] += u;
        __syncthreads();
    }
    if (t < K_NB) g_bsum[t] = sm[t] - v;          // exclusive
    if (t == 127) g_rowptr[K_NODES] = sm[127];    // total
}

// 2c) per-chunk exclusive scan -> rowptr, cursor
__global__ void k_scan_block() {
    __shared__ int sm[256];
    int b = blockIdx.x, t = threadIdx.x;
    int base = b * 1024 + t * 4;
    int c[4];
    int s = 0;
#pragma unroll
    for (int j = 0; j < 4; ++j) {
        int i = base + j;
        c[j] = (i < K_NODES) ? g_count[i] : 0;
        s += c[j];
    }
    sm[t] = s;
    __syncthreads();
    for (int o = 1; o < 256; o <<= 1) {
        int u = (t >= o) ? sm[t - o] : 0;
        __syncthreads();
        sm[t] += u;
        __syncthreads();
    }
    int off = g_bsum[b] + sm[t] - s;              // exclusive prefix
#pragma unroll
    for (int j = 0; j < 4; ++j) {
        int i = base + j;
        if (i < K_NODES) {
            g_rowptr[i] = off;
            g_cursor[i] = off;
        }
        off += c[j];
    }
}

// 3) bucket fill: sort edge srcs by dst
__global__ void k_fill(const int* __restrict__ src, const int* __restrict__ dst) {
    int i = blockIdx.x * blockDim.x + threadIdx.x;
    if (i < K_EDGES) {
        int p = atomicAdd(&g_cursor[dst[i]], 1);
        g_esrc[p] = src[i];
    }
}

// ---------------------------------------------------------------------------
// 4) SpMM mean (layer 1): one warp per dst row, gather, normalize, store
__global__ void k_spmm_mean(const float* __restrict__ X, float* __restrict__ Y) {
    int w = (blockIdx.x * blockDim.x + threadIdx.x) >> 5;
    int lane = threadIdx.x & 31;
    if (w >= K_NODES) return;
    int e0 = g_rowptr[w], e1 = g_rowptr[w + 1];
    float ax = 0.f, ay = 0.f, az = 0.f, aw = 0.f;
    int e = e0;
    for (; e + 4 <= e1; e += 4) {
        int s0 = g_esrc[e], s1 = g_esrc[e + 1], s2 = g_esrc[e + 2], s3 = g_esrc[e + 3];
        float4 v0 = *((const float4*)(X + (size_t)s0 * K_DIM) + lane);
        float4 v1 = *((const float4*)(X + (size_t)s1 * K_DIM) + lane);
        float4 v2 = *((const float4*)(X + (size_t)s2 * K_DIM) + lane);
        float4 v3 = *((const float4*)(X + (size_t)s3 * K_DIM) + lane);
        ax += v0.x + v1.x + v2.x + v3.x;
        ay += v0.y + v1.y + v2.y + v3.y;
        az += v0.z + v1.z + v2.z + v3.z;
        aw += v0.w + v1.w + v2.w + v3.w;
    }
    for (; e < e1; ++e) {
        int s = g_esrc[e];
        float4 v = *((const float4*)(X + (size_t)s * K_DIM) + lane);
        ax += v.x; ay += v.y; az += v.z; aw += v.w;
    }
    float inv = (e1 > e0) ? 1.0f / (float)(e1 - e0) : 0.0f;
    float4 r;
    r.x = ax * inv; r.y = ay * inv; r.z = az * inv; r.w = aw * inv;
    *((float4*)(Y + (size_t)w * K_DIM) + lane) = r;
}

// 4b) SpMM mean (layer 2) fused with per-graph accumulation:
//     never materializes agg(h1); adds normalized row straight into g_gs2.
__global__ void k_spmm_graph(const float* __restrict__ X, const int* __restrict__ gid) {
    int w = (blockIdx.x * blockDim.x + threadIdx.x) >> 5;
    int lane = threadIdx.x & 31;
    if (w >= K_NODES) return;
    int e0 = g_rowptr[w], e1 = g_rowptr[w + 1];
    float ax = 0.f, ay = 0.f, az = 0.f, aw = 0.f;
    int e = e0;
    for (; e + 4 <= e1; e += 4) {
        int s0 = g_esrc[e], s1 = g_esrc[e + 1], s2 = g_esrc[e + 2], s3 = g_esrc[e + 3];
        float4 v0 = *((const float4*)(X + (size_t)s0 * K_DIM) + lane);
        float4 v1 = *((const float4*)(X + (size_t)s1 * K_DIM) + lane);
        float4 v2 = *((const float4*)(X + (size_t)s2 * K_DIM) + lane);
        float4 v3 = *((const float4*)(X + (size_t)s3 * K_DIM) + lane);
        ax += v0.x + v1.x + v2.x + v3.x;
        ay += v0.y + v1.y + v2.y + v3.y;
        az += v0.z + v1.z + v2.z + v3.z;
        aw += v0.w + v1.w + v2.w + v3.w;
    }
    for (; e < e1; ++e) {
        int s = g_esrc[e];
        float4 v = *((const float4*)(X + (size_t)s * K_DIM) + lane);
        ax += v.x; ay += v.y; az += v.z; aw += v.w;
    }
    float inv = (e1 > e0) ? 1.0f / (float)(e1 - e0) : 0.0f;
    float* dstp = &g_gs2[gid[w] * K_DIM + lane * 4];
    atomicAdd(dstp + 0, ax * inv);
    atomicAdd(dstp + 1, ay * inv);
    atomicAdd(dstp + 2, az * inv);
    atomicAdd(dstp + 3, aw * inv);
}

// ---------------------------------------------------------------------------
// 5) Fused dual GEMM:  C = relu(A1@W1 + A2@W2 + bias)
//    M x 128, K = 128+128.  Block tile 128x128, thread tile 8x8, f32x2 FMA.
__global__ __launch_bounds__(256, 2)
void k_gemm_dual(const float* __restrict__ A1, const float* __restrict__ A2,
                 const float* __restrict__ W1, const float* __restrict__ W2,
                 const float* __restrict__ bias, float* __restrict__ C,
                 int M, int doRelu) {
    __shared__ __align__(16) float Xs[32 * 132];   // [k][row], padded
    __shared__ __align__(16) float Ws[32 * 128];   // [k][n]
    int tid = threadIdx.x;
    int tx = tid & 15, ty = tid >> 4;
    int rowBase = blockIdx.x * 128;
    int r0 = ty * 8, c0 = tx * 8;

    unsigned long long acc[8][4];
#pragma unroll
    for (int r = 0; r < 8; ++r)
#pragma unroll
        for (int j = 0; j < 4; ++j) acc[r][j] = 0ull;

    int rloc = tid >> 3;            // 0..31
    int kq   = (tid & 7) << 2;      // 0,4,...,28

#pragma unroll 1
    for (int ph = 0; ph < 2; ++ph) {
        const float* A = ph ? A2 : A1;
        const float* W = ph ? W2 : W1;
#pragma unroll 1
        for (int c4 = 0; c4 < 4; ++c4) {
            int k0 = c4 * 32;
            __syncthreads();
            // load W tile 32x128
#pragma unroll
            for (int i = 0; i < 4; ++i) {
                int lin = tid + i * 256;          // float4 index
                int kk = lin >> 5;
                int nn = (lin & 31) << 2;
                *(float4*)&Ws[kk * 128 + nn] =
                    *(const float4*)&W[(size_t)(k0 + kk) * K_DIM + nn];
            }
            // load X tile 128rows x 32k, transposed into Xs[k][row]
#pragma unroll
            for (int i = 0; i < 4; ++i) {
                int rr = rloc + i * 32;
                int grow = rowBase + rr;
                if (grow >= M) grow = M - 1;
                float4 v = *(const float4*)&A[(size_t)grow * K_DIM + k0 + kq];
                Xs[(kq + 0) * 132 + rr] = v.x;
                Xs[(kq + 1) * 132 + rr] = v.y;
                Xs[(kq + 2) * 132 + rr] = v.z;
                Xs[(kq + 3) * 132 + rr] = v.w;
            }
            __syncthreads();
#pragma unroll 8
            for (int k = 0; k < 32; ++k) {
                float4 a0 = *(const float4*)&Xs[k * 132 + r0];
                float4 a1 = *(const float4*)&Xs[k * 132 + r0 + 4];
                ulonglong2 wA = *(const ulonglong2*)&Ws[k * 128 + c0];
                ulonglong2 wB = *(const ulonglong2*)&Ws[k * 128 + c0 + 4];
                unsigned long long wv[4] = {wA.x, wA.y, wB.x, wB.y};
                float ar[8] = {a0.x, a0.y, a0.z, a0.w, a1.x, a1.y, a1.z, a1.w};
#pragma unroll
                for (int r = 0; r < 8; ++r) {
                    unsigned int au = __float_as_uint(ar[r]);
                    unsigned long long a2;
                    asm("mov.b64 %0, {%1, %2};" : "=l"(a2) : "r"(au), "r"(au));
#pragma unroll
                    for (int j = 0; j < 4; ++j)
                        asm("fma.rn.f32x2 %0, %1, %2, %0;"
                            : "+l"(acc[r][j]) : "l"(a2), "l"(wv[j]));
                }
            }
        }
    }

    // epilogue: bias (+ReLU), store
    float bv[8];
#pragma unroll
    for (int j = 0; j < 8; ++j) bv[j] = bias[c0 + j];
#pragma unroll
    for (int r = 0; r < 8; ++r) {
        int grow = rowBase + r0 + r;
        if (grow >= M) continue;
#pragma unroll
        for (int j = 0; j < 4; ++j) {
            float2 v;
            memcpy(&v, &acc[r][j], 8);
            v.x += bv[2 * j];
            v.y += bv[2 * j + 1];
            if (doRelu) {
                v.x = fmaxf(v.x, 0.0f);
                v.y = fmaxf(v.y, 0.0f);
            }
            *(float2*)&C[(size_t)grow * K_DIM + c0 + 2 * j] = v;
        }
    }
}

// ---------------------------------------------------------------------------
// 6) per-graph sums of h1 (graph_ids sorted -> segmented accumulation per block)
__global__ void k_graph_accum(const float* __restrict__ H, const int* __restrict__ gid) {
    int c = threadIdx.x;                 // 128
    int rs = blockIdx.x * 64;
    if (rs >= K_NODES) return;
    int re = rs + 64;
    if (re > K_NODES) re = K_NODES;
    int cur = gid[rs];
    float acc = 0.0f;
    int cnt = 0;
    for (int r = rs; r < re; ++r) {
        int g = gid[r];
        if (g != cur) {
            atomicAdd(&g_gs1[cur * K_DIM + c], acc);
            if (c == 0) atomicAdd(&g_gcnt[cur], cnt);
            acc = 0.0f; cnt = 0; cur = g;
        }
        acc += H[(size_t)r * K_DIM + c];
        ++cnt;
    }
    atomicAdd(&g_gs1[cur * K_DIM + c], acc);
    if (c == 0) atomicAdd(&g_gcnt[cur], cnt);
}

// 7) layer-2 on graph means:  hg = (gs1@W2s + gs2@W2n)/cnt + b2
__global__ void k_hg(const float* __restrict__ W2s, const float* __restrict__ W2n,
                     const float* __restrict__ b2) {
    __shared__ float s1[K_DIM], s2[K_DIM];
    int g = blockIdx.x, d = threadIdx.x;
    s1[d] = g_gs1[g * K_DIM + d];
    s2[d] = g_gs2[g * K_DIM + d];
    __syncthreads();
    float acc = 0.0f;
#pragma unroll 4
    for (int k = 0; k < K_DIM; ++k)
        acc += s1[k] * W2s[k * K_DIM + d] + s2[k] * W2n[k * K_DIM + d];
    int cnt = g_gcnt[g];
    float inv = 1.0f / (float)(cnt > 1 ? cnt : 1);
    g_hg[g * K_DIM + d] = acc * inv + b2[d];
}

// 8) classifier: out = [hg|perm] @ Wc + bc
__global__ void k_classifier(const float* __restrict__ perm,
                             const float* __restrict__ Wc,
                             const float* __restrict__ bc,
                             float* __restrict__ out) {
    int t = threadIdx.x;                 // 512
    int g = t >> 3, c = t & 7;
    float acc = bc[c];
#pragma unroll 4
    for (int k = 0; k < K_DIM; ++k)
        acc += g_hg[g * K_DIM + k] * Wc[k * K_CLS + c];
#pragma unroll 4
    for (int k = 0; k < K_DIM; ++k)
        acc += perm[g * K_DIM + k] * Wc[(K_DIM + k) * K_CLS + c];
    out[g * K_CLS + c] = acc;
}

// ---------------------------------------------------------------------------
extern "C" void kernel_launch(void* const* d_in, const int* in_sizes, int n_in,
                              void* d_out, int out_size) {
    const float* h    = (const float*)d_in[0];
    const float* perm = (const float*)d_in[1];
    const int*   src  = (const int*)  d_in[2];
    const int*   dst  = (const int*)  d_in[3];
    const int*   gid  = (const int*)  d_in[4];
    const float* W1s  = (const float*)d_in[5];
    const float* W1n  = (const float*)d_in[6];
    const float* b1   = (const float*)d_in[7];
    const float* W2s  = (const float*)d_in[8];
    const float* W2n  = (const float*)d_in[9];
    const float* b2   = (const float*)d_in[10];
    const float* Wc   = (const float*)d_in[11];
    const float* bc   = (const float*)d_in[12];
    float* out = (float*)d_out;
    (void)in_sizes; (void)n_in; (void)out_size;

    float* meanb; cudaGetSymbolAddress((void**)&meanb, g_mean);
    float* h1b;   cudaGetSymbolAddress((void**)&h1b,   g_h1);

    // CSR build
    k_zero<<<(K_NODES + 255) / 256, 256>>>();
    k_count<<<(K_EDGES + 255) / 256, 256>>>(dst);
    k_reduce_chunks<<<K_NB, 256>>>();
    k_scan_bsums<<<1, 128>>>();
    k_scan_block<<<K_NB, 256>>>();
    k_fill<<<(K_EDGES + 255) / 256, 256>>>(src, dst);

    int spmmBlocks = (K_NODES * 32 + 255) / 256;
    int gemmBlocks = (K_NODES + 127) / 128;

    // layer 1
    k_spmm_mean<<<spmmBlocks, 256>>>(h, meanb);
    k_gemm_dual<<<gemmBlocks, 256>>>(h, meanb, W1s, W1n, b1, h1b, K_NODES, 1);

    // layer 2 on graph means (linearity of mean-pool):
    k_graph_accum<<<(K_NODES + 63) / 64, 128>>>(h1b, gid);   // gs1 = per-graph sum h1
    k_spmm_graph<<<spmmBlocks, 256>>>(h1b, gid);             // gs2 = per-graph sum agg(h1)
    k_hg<<<K_GRAPHS, K_DIM>>>(W2s, W2n, b2);
    k_classifier<<<1, 512>>>(perm, Wc, bc, out);
}

// round 3
// speedup vs baseline: 2.3556x; 2.3556x over previous
#include <cuda_runtime.h>
#include <cstdint>
#include <cstring>

// ---------------------------------------------------------------------------
// GraphSAGE (2-layer, mean aggregator) + graph-mean readout + linear classifier
// Layer-2 linearity: graph-mean(h2) = graph-mean(h1)@W2s + graph-mean(agg(h1))@W2n + b2.
// Per-graph sums via segmented register accumulation (sorted graph_ids),
// NO per-node atomics (R2's same-address atomic contention cost ~500us).
// ---------------------------------------------------------------------------

#define K_NODES  100000
#define K_EDGES  1600000
#define K_GRAPHS 64
#define K_DIM    128
#define K_CLS    8
#define K_NB     98            // ceil(100000/1024)

// scratch (static device memory; no allocations)
__device__ int   g_count [K_NODES];
__device__ int   g_rowptr[K_NODES + 1];
__device__ int   g_cursor[K_NODES];
__device__ int   g_esrc  [K_EDGES];
__device__ int   g_bsum  [128];
__device__ float g_gs1   [K_GRAPHS * K_DIM];   // per-graph sum of h1
__device__ float g_gs2   [K_GRAPHS * K_DIM];   // per-graph sum of agg(h1)
__device__ int   g_gcnt  [K_GRAPHS];
__device__ float g_hg    [K_GRAPHS * K_DIM];   // per-graph mean(h2)
__device__ float g_mean  [(size_t)K_NODES * K_DIM];
__device__ float g_h1    [(size_t)K_NODES * K_DIM];

// ---------------------------------------------------------------------------
// 0) zero the per-launch accumulators
__global__ void k_zero() {
    int i = blockIdx.x * blockDim.x + threadIdx.x;
    if (i < K_NODES)           g_count[i] = 0;
    if (i < K_GRAPHS * K_DIM) { g_gs1[i] = 0.0f; g_gs2[i] = 0.0f; }
    if (i < K_GRAPHS)          g_gcnt[i] = 0;
}

// 1) histogram of dst
__global__ void k_count(const int* __restrict__ dst) {
    int i = blockIdx.x * blockDim.x + threadIdx.x;
    if (i < K_EDGES) atomicAdd(&g_count[dst[i]], 1);
}

// 2a) per-1024-chunk sums
__global__ void k_reduce_chunks() {
    __shared__ int sm[256];
    int b = blockIdx.x, t = threadIdx.x;
    int base = b * 1024 + t * 4;
    int s = 0;
#pragma unroll
    for (int j = 0; j < 4; ++j) {
        int i = base + j;
        if (i < K_NODES) s += g_count[i];
    }
    sm[t] = s;
    __syncthreads();
    for (int o = 128; o > 0; o >>= 1) {
        if (t < o) sm[t] += sm[t + o];
        __syncthreads();
    }
    if (t == 0) g_bsum[b] = sm[0];
}

// 2b) scan the chunk sums (single block)
__global__ void k_scan_bsums() {
    __shared__ int sm[128];
    int t = threadIdx.x;
    int v = (t < K_NB) ? g_bsum[t] : 0;
    sm[t] = v;
    __syncthreads();
    for (int o = 1; o < 128; o <<= 1) {
        int u = (t >= o) ? sm[t - o] : 0;
        __syncthreads();
        sm[t] += u;
        __syncthreads();
    }
    if (t < K_NB) g_bsum[t] = sm[t] - v;          // exclusive
    if (t == 127) g_rowptr[K_NODES] = sm[127];    // total
}

// 2c) per-chunk exclusive scan -> rowptr, cursor
__global__ void k_scan_block() {
    __shared__ int sm[256];
    int b = blockIdx.x, t = threadIdx.x;
    int base = b * 1024 + t * 4;
    int c[4];
    int s = 0;
#pragma unroll
    for (int j = 0; j < 4; ++j) {
        int i = base + j;
        c[j] = (i < K_NODES) ? g_count[i] : 0;
        s += c[j];
    }
    sm[t] = s;
    __syncthreads();
    for (int o = 1; o < 256; o <<= 1) {
        int u = (t >= o) ? sm[t - o] : 0;
        __syncthreads();
        sm[t] += u;
        __syncthreads();
    }
    int off = g_bsum[b] + sm[t] - s;              // exclusive prefix
#pragma unroll
    for (int j = 0; j < 4; ++j) {
        int i = base + j;
        if (i < K_NODES) {
            g_rowptr[i] = off;
            g_cursor[i] = off;
        }
        off += c[j];
    }
}

// 3) bucket fill: sort edge srcs by dst
__global__ void k_fill(const int* __restrict__ src, const int* __restrict__ dst) {
    int i = blockIdx.x * blockDim.x + threadIdx.x;
    if (i < K_EDGES) {
        int p = atomicAdd(&g_cursor[dst[i]], 1);
        g_esrc[p] = src[i];
    }
}

// ---------------------------------------------------------------------------
// 4) SpMM mean: one warp per dst row, gather, normalize, store
__global__ void k_spmm_mean(const float* __restrict__ X, float* __restrict__ Y) {
    int w = (blockIdx.x * blockDim.x + threadIdx.x) >> 5;
    int lane = threadIdx.x & 31;
    if (w >= K_NODES) return;
    int e0 = g_rowptr[w], e1 = g_rowptr[w + 1];
    float ax = 0.f, ay = 0.f, az = 0.f, aw = 0.f;
    int e = e0;
    for (; e + 4 <= e1; e += 4) {
        int s0 = g_esrc[e], s1 = g_esrc[e + 1], s2 = g_esrc[e + 2], s3 = g_esrc[e + 3];
        float4 v0 = *((const float4*)(X + (size_t)s0 * K_DIM) + lane);
        float4 v1 = *((const float4*)(X + (size_t)s1 * K_DIM) + lane);
        float4 v2 = *((const float4*)(X + (size_t)s2 * K_DIM) + lane);
        float4 v3 = *((const float4*)(X + (size_t)s3 * K_DIM) + lane);
        ax += v0.x + v1.x + v2.x + v3.x;
        ay += v0.y + v1.y + v2.y + v3.y;
        az += v0.z + v1.z + v2.z + v3.z;
        aw += v0.w + v1.w + v2.w + v3.w;
    }
    for (; e < e1; ++e) {
        int s = g_esrc[e];
        float4 v = *((const float4*)(X + (size_t)s * K_DIM) + lane);
        ax += v.x; ay += v.y; az += v.z; aw += v.w;
    }
    float inv = (e1 > e0) ? 1.0f / (float)(e1 - e0) : 0.0f;
    float4 r;
    r.x = ax * inv; r.y = ay * inv; r.z = az * inv; r.w = aw * inv;
    *((float4*)(Y + (size_t)w * K_DIM) + lane) = r;
}

// ---------------------------------------------------------------------------
// 5) Fused dual GEMM:  C = relu(A1@W1 + A2@W2 + bias)
//    M x 128, K = 128+128.  Block tile 128x128, thread tile 8x8, f32x2 FMA.
__global__ __launch_bounds__(256, 2)
void k_gemm_dual(const float* __restrict__ A1, const float* __restrict__ A2,
                 const float* __restrict__ W1, const float* __restrict__ W2,
                 const float* __restrict__ bias, float* __restrict__ C,
                 int M, int doRelu) {
    __shared__ __align__(16) float Xs[32 * 132];   // [k][row], padded
    __shared__ __align__(16) float Ws[32 * 128];   // [k][n]
    int tid = threadIdx.x;
    int tx = tid & 15, ty = tid >> 4;
    int rowBase = blockIdx.x * 128;
    int r0 = ty * 8, c0 = tx * 8;

    unsigned long long acc[8][4];
#pragma unroll
    for (int r = 0; r < 8; ++r)
#pragma unroll
        for (int j = 0; j < 4; ++j) acc[r][j] = 0ull;

    int rloc = tid >> 3;            // 0..31
    int kq   = (tid & 7) << 2;      // 0,4,...,28

#pragma unroll 1
    for (int ph = 0; ph < 2; ++ph) {
        const float* A = ph ? A2 : A1;
        const float* W = ph ? W2 : W1;
#pragma unroll 1
        for (int c4 = 0; c4 < 4; ++c4) {
            int k0 = c4 * 32;
            __syncthreads();
            // load W tile 32x128
#pragma unroll
            for (int i = 0; i < 4; ++i) {
                int lin = tid + i * 256;          // float4 index
                int kk = lin >> 5;
                int nn = (lin & 31) << 2;
                *(float4*)&Ws[kk * 128 + nn] =
                    *(const float4*)&W[(size_t)(k0 + kk) * K_DIM + nn];
            }
            // load X tile 128rows x 32k, transposed into Xs[k][row]
#pragma unroll
            for (int i = 0; i < 4; ++i) {
                int rr = rloc + i * 32;
                int grow = rowBase + rr;
                if (grow >= M) grow = M - 1;
                float4 v = *(const float4*)&A[(size_t)grow * K_DIM + k0 + kq];
                Xs[(kq + 0) * 132 + rr] = v.x;
                Xs[(kq + 1) * 132 + rr] = v.y;
                Xs[(kq + 2) * 132 + rr] = v.z;
                Xs[(kq + 3) * 132 + rr] = v.w;
            }
            __syncthreads();
#pragma unroll 8
            for (int k = 0; k < 32; ++k) {
                float4 a0 = *(const float4*)&Xs[k * 132 + r0];
                float4 a1 = *(const float4*)&Xs[k * 132 + r0 + 4];
                ulonglong2 wA = *(const ulonglong2*)&Ws[k * 128 + c0];
                ulonglong2 wB = *(const ulonglong2*)&Ws[k * 128 + c0 + 4];
                unsigned long long wv[4] = {wA.x, wA.y, wB.x, wB.y};
                float ar[8] = {a0.x, a0.y, a0.z, a0.w, a1.x, a1.y, a1.z, a1.w};
#pragma unroll
                for (int r = 0; r < 8; ++r) {
                    unsigned int au = __float_as_uint(ar[r]);
                    unsigned long long a2;
                    asm("mov.b64 %0, {%1, %2};" : "=l"(a2) : "r"(au), "r"(au));
#pragma unroll
                    for (int j = 0; j < 4; ++j)
                        asm("fma.rn.f32x2 %0, %1, %2, %0;"
                            : "+l"(acc[r][j]) : "l"(a2), "l"(wv[j]));
                }
            }
        }
    }

    // epilogue: bias (+ReLU), store
    float bv[8];
#pragma unroll
    for (int j = 0; j < 8; ++j) bv[j] = bias[c0 + j];
#pragma unroll
    for (int r = 0; r < 8; ++r) {
        int grow = rowBase + r0 + r;
        if (grow >= M) continue;
#pragma unroll
        for (int j = 0; j < 4; ++j) {
            float2 v;
            memcpy(&v, &acc[r][j], 8);
            v.x += bv[2 * j];
            v.y += bv[2 * j + 1];
            if (doRelu) {
                v.x = fmaxf(v.x, 0.0f);
                v.y = fmaxf(v.y, 0.0f);
            }
            *(float2*)&C[(size_t)grow * K_DIM + c0 + 2 * j] = v;
        }
    }
}

// ---------------------------------------------------------------------------
// 6) fused per-graph sums of h1 AND agg(h1): segmented register accumulation
//    over sorted graph_ids; atomics only at segment boundaries (~2 per block).
__global__ void k_graph_accum2(const float* __restrict__ H,
                               const float* __restrict__ Agg,
                               const int* __restrict__ gid) {
    int c = threadIdx.x;                 // 128 threads = one dim each
    int rs = blockIdx.x * 64;
    if (rs >= K_NODES) return;
    int re = rs + 64;
    if (re > K_NODES) re = K_NODES;
    int cur = gid[rs];
    float a1 = 0.0f, a2 = 0.0f;
    int cnt = 0;
    for (int r = rs; r < re; ++r) {
        int g = gid[r];
        if (g != cur) {
            atomicAdd(&g_gs1[cur * K_DIM + c], a1);
            atomicAdd(&g_gs2[cur * K_DIM + c], a2);
            if (c == 0) atomicAdd(&g_gcnt[cur], cnt);
            a1 = 0.0f; a2 = 0.0f; cnt = 0; cur = g;
        }
        a1 += H  [(size_t)r * K_DIM + c];
        a2 += Agg[(size_t)r * K_DIM + c];
        ++cnt;
    }
    atomicAdd(&g_gs1[cur * K_DIM + c], a1);
    atomicAdd(&g_gs2[cur * K_DIM + c], a2);
    if (c == 0) atomicAdd(&g_gcnt[cur], cnt);
}

// 7) layer-2 on graph means:  hg = (gs1@W2s + gs2@W2n)/cnt + b2
__global__ void k_hg(const float* __restrict__ W2s, const float* __restrict__ W2n,
                     const float* __restrict__ b2) {
    __shared__ float s1[K_DIM], s2[K_DIM];
    int g = blockIdx.x, d = threadIdx.x;
    s1[d] = g_gs1[g * K_DIM + d];
    s2[d] = g_gs2[g * K_DIM + d];
    __syncthreads();
    float acc = 0.0f;
#pragma unroll 4
    for (int k = 0; k < K_DIM; ++k)
        acc += s1[k] * W2s[k * K_DIM + d] + s2[k] * W2n[k * K_DIM + d];
    int cnt = g_gcnt[g];
    float inv = 1.0f / (float)(cnt > 1 ? cnt : 1);
    g_hg[g * K_DIM + d] = acc * inv + b2[d];
}

// 8) classifier: out = [hg|perm] @ Wc + bc
__global__ void k_classifier(const float* __restrict__ perm,
                             const float* __restrict__ Wc,
                             const float* __restrict__ bc,
                             float* __restrict__ out) {
    int t = threadIdx.x;                 // 512
    int g = t >> 3, c = t & 7;
    float acc = bc[c];
#pragma unroll 4
    for (int k = 0; k < K_DIM; ++k)
        acc += g_hg[g * K_DIM + k] * Wc[k * K_CLS + c];
#pragma unroll 4
    for (int k = 0; k < K_DIM; ++k)
        acc += perm[g * K_DIM + k] * Wc[(K_DIM + k) * K_CLS + c];
    out[g * K_CLS + c] = acc;
}

// ---------------------------------------------------------------------------
extern "C" void kernel_launch(void* const* d_in, const int* in_sizes, int n_in,
                              void* d_out, int out_size) {
    const float* h    = (const float*)d_in[0];
    const float* perm = (const float*)d_in[1];
    const int*   src  = (const int*)  d_in[2];
    const int*   dst  = (const int*)  d_in[3];
    const int*   gid  = (const int*)  d_in[4];
    const float* W1s  = (const float*)d_in[5];
    const float* W1n  = (const float*)d_in[6];
    const float* b1   = (const float*)d_in[7];
    const float* W2s  = (const float*)d_in[8];
    const float* W2n  = (const float*)d_in[9];
    const float* b2   = (const float*)d_in[10];
    const float* Wc   = (const float*)d_in[11];
    const float* bc   = (const float*)d_in[12];
    float* out = (float*)d_out;
    (void)in_sizes; (void)n_in; (void)out_size;

    float* meanb; cudaGetSymbolAddress((void**)&meanb, g_mean);
    float* h1b;   cudaGetSymbolAddress((void**)&h1b,   g_h1);

    // CSR build
    k_zero<<<(K_NODES + 255) / 256, 256>>>();
    k_count<<<(K_EDGES + 255) / 256, 256>>>(dst);
    k_reduce_chunks<<<K_NB, 256>>>();
    k_scan_bsums<<<1, 128>>>();
    k_scan_block<<<K_NB, 256>>>();
    k_fill<<<(K_EDGES + 255) / 256, 256>>>(src, dst);

    int spmmBlocks = (K_NODES * 32 + 255) / 256;
    int gemmBlocks = (K_NODES + 127) / 128;

    // layer 1
    k_spmm_mean<<<spmmBlocks, 256>>>(h, meanb);
    k_gemm_dual<<<gemmBlocks, 256>>>(h, meanb, W1s, W1n, b1, h1b, K_NODES, 1);

    // layer 2 on graph means (linearity of mean-pool), no per-node atomics:
    k_spmm_mean<<<spmmBlocks, 256>>>(h1b, meanb);                 // agg(h1)
    k_graph_accum2<<<(K_NODES + 63) / 64, 128>>>(h1b, meanb, gid);
    k_hg<<<K_GRAPHS, K_DIM>>>(W2s, W2n, b2);
    k_classifier<<<1, 512>>>(perm, Wc, bc, out);
}

// round 5
// speedup vs baseline: 2.8122x; 1.1938x over previous
#include <cuda_runtime.h>
#include <cstdint>
#include <cstring>

// ---------------------------------------------------------------------------
// GraphSAGE (2-layer, mean agg) + graph-mean readout + linear classifier.
// R5: layer-1 dual GEMM on warp-level mma.sync tf32 (tensor pipe, no tcgen05 —
// harness PTX target is compute_103 which gates tcgen05).  Rest = R3 (397us).
// ---------------------------------------------------------------------------

#define K_NODES  100000
#define K_EDGES  1600000
#define K_GRAPHS 64
#define K_DIM    128
#define K_CLS    8
#define K_NB     98            // ceil(100000/1024)

// scratch (static device memory; no allocations)
__device__ int   g_count [K_NODES];
__device__ int   g_rowptr[K_NODES + 1];
__device__ int   g_cursor[K_NODES];
__device__ int   g_esrc  [K_EDGES];
__device__ int   g_bsum  [128];
__device__ float g_gs1   [K_GRAPHS * K_DIM];
__device__ float g_gs2   [K_GRAPHS * K_DIM];
__device__ int   g_gcnt  [K_GRAPHS];
__device__ float g_hg    [K_GRAPHS * K_DIM];
__device__ float g_mean  [(size_t)K_NODES * K_DIM];
__device__ float g_h1    [(size_t)K_NODES * K_DIM];

// ---------------------------------------------------------------------------
// 0) zero the per-launch accumulators
__global__ void k_zero() {
    int i = blockIdx.x * blockDim.x + threadIdx.x;
    if (i < K_NODES)           g_count[i] = 0;
    if (i < K_GRAPHS * K_DIM) { g_gs1[i] = 0.0f; g_gs2[i] = 0.0f; }
    if (i < K_GRAPHS)          g_gcnt[i] = 0;
}

// 1) histogram of dst
__global__ void k_count(const int* __restrict__ dst) {
    int i = blockIdx.x * blockDim.x + threadIdx.x;
    if (i < K_EDGES) atomicAdd(&g_count[dst[i]], 1);
}

// 2a) per-1024-chunk sums
__global__ void k_reduce_chunks() {
    __shared__ int sm[256];
    int b = blockIdx.x, t = threadIdx.x;
    int base = b * 1024 + t * 4;
    int s = 0;
#pragma unroll
    for (int j = 0; j < 4; ++j) {
        int i = base + j;
        if (i < K_NODES) s += g_count[i];
    }
    sm[t] = s;
    __syncthreads();
    for (int o = 128; o > 0; o >>= 1) {
        if (t < o) sm[t] += sm[t + o];
        __syncthreads();
    }
    if (t == 0) g_bsum[b] = sm[0];
}

// 2b) scan the chunk sums (single block)
__global__ void k_scan_bsums() {
    __shared__ int sm[128];
    int t = threadIdx.x;
    int v = (t < K_NB) ? g_bsum[t] : 0;
    sm[t] = v;
    __syncthreads();
    for (int o = 1; o < 128; o <<= 1) {
        int u = (t >= o) ? sm[t - o] : 0;
        __syncthreads();
        sm[t] += u;
        __syncthreads();
    }
    if (t < K_NB) g_bsum[t] = sm[t] - v;
    if (t == 127) g_rowptr[K_NODES] = sm[127];
}

// 2c) per-chunk exclusive scan -> rowptr, cursor
__global__ void k_scan_block() {
    __shared__ int sm[256];
    int b = blockIdx.x, t = threadIdx.x;
    int base = b * 1024 + t * 4;
    int c[4];
    int s = 0;
#pragma unroll
    for (int j = 0; j < 4; ++j) {
        int i = base + j;
        c[j] = (i < K_NODES) ? g_count[i] : 0;
        s += c[j];
    }
    sm[t] = s;
    __syncthreads();
    for (int o = 1; o < 256; o <<= 1) {
        int u = (t >= o) ? sm[t - o] : 0;
        __syncthreads();
        sm[t] += u;
        __syncthreads();
    }
    int off = g_bsum[b] + sm[t] - s;
#pragma unroll
    for (int j = 0; j < 4; ++j) {
        int i = base + j;
        if (i < K_NODES) {
            g_rowptr[i] = off;
            g_cursor[i] = off;
        }
        off += c[j];
    }
}

// 3) bucket fill: sort edge srcs by dst
__global__ void k_fill(const int* __restrict__ src, const int* __restrict__ dst) {
    int i = blockIdx.x * blockDim.x + threadIdx.x;
    if (i < K_EDGES) {
        int p = atomicAdd(&g_cursor[dst[i]], 1);
        g_esrc[p] = src[i];
    }
}

// ---------------------------------------------------------------------------
// 4) SpMM mean: one warp per dst row, gather, normalize, store
__global__ void k_spmm_mean(const float* __restrict__ X, float* __restrict__ Y) {
    int w = (blockIdx.x * blockDim.x + threadIdx.x) >> 5;
    int lane = threadIdx.x & 31;
    if (w >= K_NODES) return;
    int e0 = g_rowptr[w], e1 = g_rowptr[w + 1];
    float ax = 0.f, ay = 0.f, az = 0.f, aw = 0.f;
    int e = e0;
    for (; e + 4 <= e1; e += 4) {
        int s0 = g_esrc[e], s1 = g_esrc[e + 1], s2 = g_esrc[e + 2], s3 = g_esrc[e + 3];
        float4 v0 = *((const float4*)(X + (size_t)s0 * K_DIM) + lane);
        float4 v1 = *((const float4*)(X + (size_t)s1 * K_DIM) + lane);
        float4 v2 = *((const float4*)(X + (size_t)s2 * K_DIM) + lane);
        float4 v3 = *((const float4*)(X + (size_t)s3 * K_DIM) + lane);
        ax += v0.x + v1.x + v2.x + v3.x;
        ay += v0.y + v1.y + v2.y + v3.y;
        az += v0.z + v1.z + v2.z + v3.z;
        aw += v0.w + v1.w + v2.w + v3.w;
    }
    for (; e < e1; ++e) {
        int s = g_esrc[e];
        float4 v = *((const float4*)(X + (size_t)s * K_DIM) + lane);
        ax += v.x; ay += v.y; az += v.z; aw += v.w;
    }
    float inv = (e1 > e0) ? 1.0f / (float)(e1 - e0) : 0.0f;
    float4 r;
    r.x = ax * inv; r.y = ay * inv; r.z = az * inv; r.w = aw * inv;
    *((float4*)(Y + (size_t)w * K_DIM) + lane) = r;
}

// ---------------------------------------------------------------------------
// 5) mma.sync tf32 dual GEMM: h1 = relu(A1@W1 + A2@W2 + bias)
//    Block 128(M)x128(N), 8 warps (4x2), warp tile 32x64, m16n8k8.
__device__ __forceinline__ uint32_t f2tf32(float x) {
    uint32_t u;
    asm("cvt.rna.tf32.f32 %0, %1;" : "=r"(u) : "f"(x));
    return u;
}
__device__ __forceinline__ void mma_tf32(float* c, uint32_t a0, uint32_t a1,
                                         uint32_t a2, uint32_t a3,
                                         uint32_t b0, uint32_t b1) {
    asm volatile(
        "mma.sync.aligned.m16n8k8.row.col.f32.tf32.tf32.f32 "
        "{%0,%1,%2,%3}, {%4,%5,%6,%7}, {%8,%9}, {%0,%1,%2,%3};"
        : "+f"(c[0]), "+f"(c[1]), "+f"(c[2]), "+f"(c[3])
        : "r"(a0), "r"(a1), "r"(a2), "r"(a3), "r"(b0), "r"(b1));
}

__global__ __launch_bounds__(256, 2)
void k_gemm_mma(const float* __restrict__ A1, const float* __restrict__ A2,
                const float* __restrict__ W1, const float* __restrict__ W2,
                const float* __restrict__ bias, float* __restrict__ C, int M) {
    __shared__ __align__(16) uint32_t Xs[32 * 132];   // tf32 bits, [k][row] padded
    __shared__ __align__(16) uint32_t Ws[32 * 128];   // tf32 bits, [k][n]
    int tid = threadIdx.x, wid = tid >> 5, lane = tid & 31;
    int grp = lane >> 2, tig = lane & 3;
    int warpM = wid & 3, warpN = wid >> 2;       // 4 x 2
    int rowBase = blockIdx.x * 128;
    int wr = warpM * 32;                          // warp row offset in tile
    int wn = warpN * 64;                          // warp col offset

    float acc[2][8][4];
#pragma unroll
    for (int mt = 0; mt < 2; ++mt)
#pragma unroll
        for (int nt = 0; nt < 8; ++nt)
#pragma unroll
            for (int q = 0; q < 4; ++q) acc[mt][nt][q] = 0.0f;

#pragma unroll 1
    for (int ph = 0; ph < 2; ++ph) {
        const float* A = ph ? A2 : A1;
        const float* W = ph ? W2 : W1;
#pragma unroll 1
        for (int c4 = 0; c4 < 4; ++c4) {
            int k0 = c4 * 32;
            __syncthreads();
            // stage A tile transposed: Xs[k][row], 128 rows x 32 k
            {
                int rloc = tid >> 3;            // 0..31
                int kq   = (tid & 7) << 2;      // 0..28 step 4
#pragma unroll
                for (int i = 0; i < 4; ++i) {
                    int rr = rloc + i * 32;
                    int grow = rowBase + rr; if (grow >= M) grow = M - 1;
                    float4 v = *(const float4*)&A[(size_t)grow * K_DIM + k0 + kq];
                    Xs[(kq + 0) * 132 + rr] = f2tf32(v.x);
                    Xs[(kq + 1) * 132 + rr] = f2tf32(v.y);
                    Xs[(kq + 2) * 132 + rr] = f2tf32(v.z);
                    Xs[(kq + 3) * 132 + rr] = f2tf32(v.w);
                }
            }
            // stage W tile: Ws[k][n], 32 k x 128 n
            {
#pragma unroll
                for (int i = 0; i < 4; ++i) {
                    int lin = tid + i * 256;       // float4 slot
                    int kk = lin >> 5;
                    int nn = (lin & 31) << 2;
                    float4 v = *(const float4*)&W[(size_t)(k0 + kk) * K_DIM + nn];
                    Ws[kk * 128 + nn + 0] = f2tf32(v.x);
                    Ws[kk * 128 + nn + 1] = f2tf32(v.y);
                    Ws[kk * 128 + nn + 2] = f2tf32(v.z);
                    Ws[kk * 128 + nn + 3] = f2tf32(v.w);
                }
            }
            __syncthreads();
#pragma unroll
            for (int ks = 0; ks < 4; ++ks) {       // 8 k per step
                int kk = ks * 8;
                uint32_t af[2][4];
#pragma unroll
                for (int mt = 0; mt < 2; ++mt) {
                    int r = wr + mt * 16 + grp;
                    af[mt][0] = Xs[(kk + tig)     * 132 + r];
                    af[mt][1] = Xs[(kk + tig)     * 132 + r + 8];
                    af[mt][2] = Xs[(kk + tig + 4) * 132 + r];
                    af[mt][3] = Xs[(kk + tig + 4) * 132 + r + 8];
                }
#pragma unroll
                for (int nt = 0; nt < 8; ++nt) {
                    int n = wn + nt * 8 + grp;
                    uint32_t b0 = Ws[(kk + tig)     * 128 + n];
                    uint32_t b1 = Ws[(kk + tig + 4) * 128 + n];
                    mma_tf32(acc[0][nt], af[0][0], af[0][1], af[0][2], af[0][3], b0, b1);
                    mma_tf32(acc[1][nt], af[1][0], af[1][1], af[1][2], af[1][3], b0, b1);
                }
            }
        }
    }

    // epilogue: bias + ReLU, float2 stores
#pragma unroll
    for (int mt = 0; mt < 2; ++mt) {
        int r0g = rowBase + wr + mt * 16 + grp;
        int r1g = r0g + 8;
#pragma unroll
        for (int nt = 0; nt < 8; ++nt) {
            int col = wn + nt * 8 + 2 * tig;
            float2 bv = *(const float2*)&bias[col];
            if (r0g < M) {
                float2 v;
                v.x = fmaxf(acc[mt][nt][0] + bv.x, 0.0f);
                v.y = fmaxf(acc[mt][nt][1] + bv.y, 0.0f);
                *(float2*)&C[(size_t)r0g * K_DIM + col] = v;
            }
            if (r1g < M) {
                float2 v;
                v.x = fmaxf(acc[mt][nt][2] + bv.x, 0.0f);
                v.y = fmaxf(acc[mt][nt][3] + bv.y, 0.0f);
                *(float2*)&C[(size_t)r1g * K_DIM + col] = v;
            }
        }
    }
}

// ---------------------------------------------------------------------------
// 6) fused per-graph sums of h1 AND agg(h1): segmented register accumulation
__global__ void k_graph_accum2(const float* __restrict__ H,
                               const float* __restrict__ Agg,
                               const int* __restrict__ gid) {
    int c = threadIdx.x;                 // 128 threads = one dim each
    int rs = blockIdx.x * 64;
    if (rs >= K_NODES) return;
    int re = rs + 64;
    if (re > K_NODES) re = K_NODES;
    int cur = gid[rs];
    float a1 = 0.0f, a2 = 0.0f;
    int cnt = 0;
    for (int r = rs; r < re; ++r) {
        int g = gid[r];
        if (g != cur) {
            atomicAdd(&g_gs1[cur * K_DIM + c], a1);
            atomicAdd(&g_gs2[cur * K_DIM + c], a2);
            if (c == 0) atomicAdd(&g_gcnt[cur], cnt);
            a1 = 0.0f; a2 = 0.0f; cnt = 0; cur = g;
        }
        a1 += H  [(size_t)r * K_DIM + c];
        a2 += Agg[(size_t)r * K_DIM + c];
        ++cnt;
    }
    atomicAdd(&g_gs1[cur * K_DIM + c], a1);
    atomicAdd(&g_gs2[cur * K_DIM + c], a2);
    if (c == 0) atomicAdd(&g_gcnt[cur], cnt);
}

// 7) layer-2 on graph means:  hg = (gs1@W2s + gs2@W2n)/cnt + b2
__global__ void k_hg(const float* __restrict__ W2s, const float* __restrict__ W2n,
                     const float* __restrict__ b2) {
    __shared__ float s1[K_DIM], s2[K_DIM];
    int g = blockIdx.x, d = threadIdx.x;
    s1[d] = g_gs1[g * K_DIM + d];
    s2[d] = g_gs2[g * K_DIM + d];
    __syncthreads();
    float acc = 0.0f;
#pragma unroll 4
    for (int k = 0; k < K_DIM; ++k)
        acc += s1[k] * W2s[k * K_DIM + d] + s2[k] * W2n[k * K_DIM + d];
    int cnt = g_gcnt[g];
    float inv = 1.0f / (float)(cnt > 1 ? cnt : 1);
    g_hg[g * K_DIM + d] = acc * inv + b2[d];
}

// 8) classifier: out = [hg|perm] @ Wc + bc
__global__ void k_classifier(const float* __restrict__ perm,
                             const float* __restrict__ Wc,
                             const float* __restrict__ bc,
                             float* __restrict__ out) {
    int t = threadIdx.x;                 // 512
    int g = t >> 3, c = t & 7;
    float acc = bc[c];
#pragma unroll 4
    for (int k = 0; k < K_DIM; ++k)
        acc += g_hg[g * K_DIM + k] * Wc[k * K_CLS + c];
#pragma unroll 4
    for (int k = 0; k < K_DIM; ++k)
        acc += perm[g * K_DIM + k] * Wc[(K_DIM + k) * K_CLS + c];
    out[g * K_CLS + c] = acc;
}

// ---------------------------------------------------------------------------
extern "C" void kernel_launch(void* const* d_in, const int* in_sizes, int n_in,
                              void* d_out, int out_size) {
    const float* h    = (const float*)d_in[0];
    const float* perm = (const float*)d_in[1];
    const int*   src  = (const int*)  d_in[2];
    const int*   dst  = (const int*)  d_in[3];
    const int*   gid  = (const int*)  d_in[4];
    const float* W1s  = (const float*)d_in[5];
    const float* W1n  = (const float*)d_in[6];
    const float* b1   = (const float*)d_in[7];
    const float* W2s  = (const float*)d_in[8];
    const float* W2n  = (const float*)d_in[9];
    const float* b2   = (const float*)d_in[10];
    const float* Wc   = (const float*)d_in[11];
    const float* bc   = (const float*)d_in[12];
    float* out = (float*)d_out;
    (void)in_sizes; (void)n_in; (void)out_size;

    float* meanb; cudaGetSymbolAddress((void**)&meanb, g_mean);
    float* h1b;   cudaGetSymbolAddress((void**)&h1b,   g_h1);

    // CSR build
    k_zero<<<(K_NODES + 255) / 256, 256>>>();
    k_count<<<(K_EDGES + 255) / 256, 256>>>(dst);
    k_reduce_chunks<<<K_NB, 256>>>();
    k_scan_bsums<<<1, 128>>>();
    k_scan_block<<<K_NB, 256>>>();
    k_fill<<<(K_EDGES + 255) / 256, 256>>>(src, dst);

    int spmmBlocks = (K_NODES * 32 + 255) / 256;
    int gemmBlocks = (K_NODES + 127) / 128;

    // layer 1 (tf32 mma GEMM)
    k_spmm_mean<<<spmmBlocks, 256>>>(h, meanb);
    k_gemm_mma<<<gemmBlocks, 256>>>(h, meanb, W1s, W1n, b1, h1b, K_NODES);

    // layer 2 on graph means (linearity of mean-pool), no per-node atomics:
    k_spmm_mean<<<spmmBlocks, 256>>>(h1b, meanb);                 // agg(h1)
    k_graph_accum2<<<(K_NODES + 63) / 64, 128>>>(h1b, meanb, gid);
    k_hg<<<K_GRAPHS, K_DIM>>>(W2s, W2n, b2);
    k_classifier<<<1, 512>>>(perm, Wc, bc, out);
}

// round 6
// speedup vs baseline: 2.8527x; 1.0144x over previous
#include <cuda_runtime.h>
#include <cuda_bf16.h>
#include <cstdint>
#include <cstring>

// ---------------------------------------------------------------------------
// GraphSAGE (2-layer, mean agg) + graph-mean readout + linear classifier.
// R6: SpMM gathers run on bf16 shadows of h / h1 (half the L2 gather traffic,
// which is the dominant roofline term).  fp32 accumulation throughout.
// GEMM = tf32 mma.sync (R5).  Layer-2 via graph-mean linearity (R3).
// ---------------------------------------------------------------------------

#define K_NODES  100000
#define K_EDGES  1600000
#define K_GRAPHS 64
#define K_DIM    128
#define K_CLS    8
#define K_NB     98            // ceil(100000/1024)

// scratch (static device memory; no allocations)
__device__ int   g_count [K_NODES];
__device__ int   g_rowptr[K_NODES + 1];
__device__ int   g_cursor[K_NODES];
__device__ int   g_esrc  [K_EDGES];
__device__ int   g_bsum  [128];
__device__ float g_gs1   [K_GRAPHS * K_DIM];
__device__ float g_gs2   [K_GRAPHS * K_DIM];
__device__ int   g_gcnt  [K_GRAPHS];
__device__ float g_hg    [K_GRAPHS * K_DIM];
__device__ float g_mean  [(size_t)K_NODES * K_DIM];
__device__ float g_h1    [(size_t)K_NODES * K_DIM];
__device__ __nv_bfloat16 g_hb  [(size_t)K_NODES * K_DIM];   // bf16 shadow of h
__device__ __nv_bfloat16 g_h1b [(size_t)K_NODES * K_DIM];   // bf16 shadow of h1

// ---------------------------------------------------------------------------
// 0) zero the per-launch accumulators
__global__ void k_zero() {
    int i = blockIdx.x * blockDim.x + threadIdx.x;
    if (i < K_NODES)           g_count[i] = 0;
    if (i < K_GRAPHS * K_DIM) { g_gs1[i] = 0.0f; g_gs2[i] = 0.0f; }
    if (i < K_GRAPHS)          g_gcnt[i] = 0;
}

// 0b) h -> bf16 shadow
__global__ void k_tobf16(const float* __restrict__ X, __nv_bfloat16* __restrict__ Y,
                         int nquads) {
    int i = blockIdx.x * blockDim.x + threadIdx.x;
    if (i >= nquads) return;
    float4 v = *((const float4*)X + i);
    __nv_bfloat162 a = __floats2bfloat162_rn(v.x, v.y);
    __nv_bfloat162 b = __floats2bfloat162_rn(v.z, v.w);
    uint2 u;
    memcpy(&u.x, &a, 4);
    memcpy(&u.y, &b, 4);
    *((uint2*)Y + i) = u;
}

// 1) histogram of dst
__global__ void k_count(const int* __restrict__ dst) {
    int i = blockIdx.x * blockDim.x + threadIdx.x;
    if (i < K_EDGES) atomicAdd(&g_count[dst[i]], 1);
}

// 2a) per-1024-chunk sums
__global__ void k_reduce_chunks() {
    __shared__ int sm[256];
    int b = blockIdx.x, t = threadIdx.x;
    int base = b * 1024 + t * 4;
    int s = 0;
#pragma unroll
    for (int j = 0; j < 4; ++j) {
        int i = base + j;
        if (i < K_NODES) s += g_count[i];
    }
    sm[t] = s;
    __syncthreads();
    for (int o = 128; o > 0; o >>= 1) {
        if (t < o) sm[t] += sm[t + o];
        __syncthreads();
    }
    if (t == 0) g_bsum[b] = sm[0];
}

// 2b) scan the chunk sums (single block)
__global__ void k_scan_bsums() {
    __shared__ int sm[128];
    int t = threadIdx.x;
    int v = (t < K_NB) ? g_bsum[t] : 0;
    sm[t] = v;
    __syncthreads();
    for (int o = 1; o < 128; o <<= 1) {
        int u = (t >= o) ? sm[t - o] : 0;
        __syncthreads();
        sm[t] += u;
        __syncthreads();
    }
    if (t < K_NB) g_bsum[t] = sm[t] - v;
    if (t == 127) g_rowptr[K_NODES] = sm[127];
}

// 2c) per-chunk exclusive scan -> rowptr, cursor
__global__ void k_scan_block() {
    __shared__ int sm[256];
    int b = blockIdx.x, t = threadIdx.x;
    int base = b * 1024 + t * 4;
    int c[4];
    int s = 0;
#pragma unroll
    for (int j = 0; j < 4; ++j) {
        int i = base + j;
        c[j] = (i < K_NODES) ? g_count[i] : 0;
        s += c[j];
    }
    sm[t] = s;
    __syncthreads();
    for (int o = 1; o < 256; o <<= 1) {
        int u = (t >= o) ? sm[t - o] : 0;
        __syncthreads();
        sm[t] += u;
        __syncthreads();
    }
    int off = g_bsum[b] + sm[t] - s;
#pragma unroll
    for (int j = 0; j < 4; ++j) {
        int i = base + j;
        if (i < K_NODES) {
            g_rowptr[i] = off;
            g_cursor[i] = off;
        }
        off += c[j];
    }
}

// 3) bucket fill: sort edge srcs by dst
__global__ void k_fill(const int* __restrict__ src, const int* __restrict__ dst) {
    int i = blockIdx.x * blockDim.x + threadIdx.x;
    if (i < K_EDGES) {
        int p = atomicAdd(&g_cursor[dst[i]], 1);
        g_esrc[p] = src[i];
    }
}

// ---------------------------------------------------------------------------
// 4) SpMM mean over bf16 rows: one warp per dst row; lane holds 4 dims (8B/lane)
__global__ void k_spmm_bf16(const __nv_bfloat16* __restrict__ X, float* __restrict__ Y) {
    int w = (blockIdx.x * blockDim.x + threadIdx.x) >> 5;
    int lane = threadIdx.x & 31;
    if (w >= K_NODES) return;
    int e0 = g_rowptr[w], e1 = g_rowptr[w + 1];
    float ax = 0.f, ay = 0.f, az = 0.f, aw = 0.f;
    int e = e0;
    for (; e + 4 <= e1; e += 4) {
        int s0 = g_esrc[e], s1 = g_esrc[e + 1], s2 = g_esrc[e + 2], s3 = g_esrc[e + 3];
        uint2 u0 = *((const uint2*)(X + (size_t)s0 * K_DIM) + lane);
        uint2 u1 = *((const uint2*)(X + (size_t)s1 * K_DIM) + lane);
        uint2 u2 = *((const uint2*)(X + (size_t)s2 * K_DIM) + lane);
        uint2 u3 = *((const uint2*)(X + (size_t)s3 * K_DIM) + lane);
#pragma unroll
        for (int q = 0; q < 4; ++q) {
            uint2 u = (q == 0) ? u0 : (q == 1) ? u1 : (q == 2) ? u2 : u3;
            __nv_bfloat162 p0, p1;
            memcpy(&p0, &u.x, 4);
            memcpy(&p1, &u.y, 4);
            float2 f0 = __bfloat1622float2(p0);
            float2 f1 = __bfloat1622float2(p1);
            ax += f0.x; ay += f0.y; az += f1.x; aw += f1.y;
        }
    }
    for (; e < e1; ++e) {
        int s = g_esrc[e];
        uint2 u = *((const uint2*)(X + (size_t)s * K_DIM) + lane);
        __nv_bfloat162 p0, p1;
        memcpy(&p0, &u.x, 4);
        memcpy(&p1, &u.y, 4);
        float2 f0 = __bfloat1622float2(p0);
        float2 f1 = __bfloat1622float2(p1);
        ax += f0.x; ay += f0.y; az += f1.x; aw += f1.y;
    }
    float inv = (e1 > e0) ? 1.0f / (float)(e1 - e0) : 0.0f;
    float4 r;
    r.x = ax * inv; r.y = ay * inv; r.z = az * inv; r.w = aw * inv;
    *((float4*)(Y + (size_t)w * K_DIM) + lane) = r;
}

// ---------------------------------------------------------------------------
// 5) mma.sync tf32 dual GEMM: h1 = relu(A1@W1 + A2@W2 + bias)
//    Also writes a bf16 shadow of h1 for the layer-2 gather.
__device__ __forceinline__ uint32_t f2tf32(float x) {
    uint32_t u;
    asm("cvt.rna.tf32.f32 %0, %1;" : "=r"(u) : "f"(x));
    return u;
}
__device__ __forceinline__ void mma_tf32(float* c, uint32_t a0, uint32_t a1,
                                         uint32_t a2, uint32_t a3,
                                         uint32_t b0, uint32_t b1) {
    asm volatile(
        "mma.sync.aligned.m16n8k8.row.col.f32.tf32.tf32.f32 "
        "{%0,%1,%2,%3}, {%4,%5,%6,%7}, {%8,%9}, {%0,%1,%2,%3};"
        : "+f"(c[0]), "+f"(c[1]), "+f"(c[2]), "+f"(c[3])
        : "r"(a0), "r"(a1), "r"(a2), "r"(a3), "r"(b0), "r"(b1));
}

__global__ __launch_bounds__(256, 2)
void k_gemm_mma(const float* __restrict__ A1, const float* __restrict__ A2,
                const float* __restrict__ W1, const float* __restrict__ W2,
                const float* __restrict__ bias, float* __restrict__ C,
                __nv_bfloat16* __restrict__ Cb, int M) {
    __shared__ __align__(16) uint32_t Xs[32 * 132];   // tf32 bits, [k][row] padded
    __shared__ __align__(16) uint32_t Ws[32 * 128];   // tf32 bits, [k][n]
    int tid = threadIdx.x, wid = tid >> 5, lane = tid & 31;
    int grp = lane >> 2, tig = lane & 3;
    int warpM = wid & 3, warpN = wid >> 2;       // 4 x 2
    int rowBase = blockIdx.x * 128;
    int wr = warpM * 32;
    int wn = warpN * 64;

    float acc[2][8][4];
#pragma unroll
    for (int mt = 0; mt < 2; ++mt)
#pragma unroll
        for (int nt = 0; nt < 8; ++nt)
#pragma unroll
            for (int q = 0; q < 4; ++q) acc[mt][nt][q] = 0.0f;

#pragma unroll 1
    for (int ph = 0; ph < 2; ++ph) {
        const float* A = ph ? A2 : A1;
        const float* W = ph ? W2 : W1;
#pragma unroll 1
        for (int c4 = 0; c4 < 4; ++c4) {
            int k0 = c4 * 32;
            __syncthreads();
            {
                int rloc = tid >> 3;
                int kq   = (tid & 7) << 2;
#pragma unroll
                for (int i = 0; i < 4; ++i) {
                    int rr = rloc + i * 32;
                    int grow = rowBase + rr; if (grow >= M) grow = M - 1;
                    float4 v = *(const float4*)&A[(size_t)grow * K_DIM + k0 + kq];
                    Xs[(kq + 0) * 132 + rr] = f2tf32(v.x);
                    Xs[(kq + 1) * 132 + rr] = f2tf32(v.y);
                    Xs[(kq + 2) * 132 + rr] = f2tf32(v.z);
                    Xs[(kq + 3) * 132 + rr] = f2tf32(v.w);
                }
            }
            {
#pragma unroll
                for (int i = 0; i < 4; ++i) {
                    int lin = tid + i * 256;
                    int kk = lin >> 5;
                    int nn = (lin & 31) << 2;
                    float4 v = *(const float4*)&W[(size_t)(k0 + kk) * K_DIM + nn];
                    Ws[kk * 128 + nn + 0] = f2tf32(v.x);
                    Ws[kk * 128 + nn + 1] = f2tf32(v.y);
                    Ws[kk * 128 + nn + 2] = f2tf32(v.z);
                    Ws[kk * 128 + nn + 3] = f2tf32(v.w);
                }
            }
            __syncthreads();
#pragma unroll
            for (int ks = 0; ks < 4; ++ks) {
                int kk = ks * 8;
                uint32_t af[2][4];
#pragma unroll
                for (int mt = 0; mt < 2; ++mt) {
                    int r = wr + mt * 16 + grp;
                    af[mt][0] = Xs[(kk + tig)     * 132 + r];
                    af[mt][1] = Xs[(kk + tig)     * 132 + r + 8];
                    af[mt][2] = Xs[(kk + tig + 4) * 132 + r];
                    af[mt][3] = Xs[(kk + tig + 4) * 132 + r + 8];
                }
#pragma unroll
                for (int nt = 0; nt < 8; ++nt) {
                    int n = wn + nt * 8 + grp;
                    uint32_t b0 = Ws[(kk + tig)     * 128 + n];
                    uint32_t b1 = Ws[(kk + tig + 4) * 128 + n];
                    mma_tf32(acc[0][nt], af[0][0], af[0][1], af[0][2], af[0][3], b0, b1);
                    mma_tf32(acc[1][nt], af[1][0], af[1][1], af[1][2], af[1][3], b0, b1);
                }
            }
        }
    }

    // epilogue: bias + ReLU; fp32 store + bf16 shadow store
#pragma unroll
    for (int mt = 0; mt < 2; ++mt) {
        int r0g = rowBase + wr + mt * 16 + grp;
        int r1g = r0g + 8;
#pragma unroll
        for (int nt = 0; nt < 8; ++nt) {
            int col = wn + nt * 8 + 2 * tig;
            float2 bv = *(const float2*)&bias[col];
            if (r0g < M) {
                float2 v;
                v.x = fmaxf(acc[mt][nt][0] + bv.x, 0.0f);
                v.y = fmaxf(acc[mt][nt][1] + bv.y, 0.0f);
                *(float2*)&C[(size_t)r0g * K_DIM + col] = v;
                __nv_bfloat162 hb = __floats2bfloat162_rn(v.x, v.y);
                *(__nv_bfloat162*)&Cb[(size_t)r0g * K_DIM + col] = hb;
            }
            if (r1g < M) {
                float2 v;
                v.x = fmaxf(acc[mt][nt][2] + bv.x, 0.0f);
                v.y = fmaxf(acc[mt][nt][3] + bv.y, 0.0f);
                *(float2*)&C[(size_t)r1g * K_DIM + col] = v;
                __nv_bfloat162 hb = __floats2bfloat162_rn(v.x, v.y);
                *(__nv_bfloat162*)&Cb[(size_t)r1g * K_DIM + col] = hb;
            }
        }
    }
}

// ---------------------------------------------------------------------------
// 6) fused per-graph sums of h1 AND agg(h1): segmented register accumulation
__global__ void k_graph_accum2(const float* __restrict__ H,
                               const float* __restrict__ Agg,
                               const int* __restrict__ gid) {
    int c = threadIdx.x;                 // 128 threads = one dim each
    int rs = blockIdx.x * 64;
    if (rs >= K_NODES) return;
    int re = rs + 64;
    if (re > K_NODES) re = K_NODES;
    int cur = gid[rs];
    float a1 = 0.0f, a2 = 0.0f;
    int cnt = 0;
    for (int r = rs; r < re; ++r) {
        int g = gid[r];
        if (g != cur) {
            atomicAdd(&g_gs1[cur * K_DIM + c], a1);
            atomicAdd(&g_gs2[cur * K_DIM + c], a2);
            if (c == 0) atomicAdd(&g_gcnt[cur], cnt);
            a1 = 0.0f; a2 = 0.0f; cnt = 0; cur = g;
        }
        a1 += H  [(size_t)r * K_DIM + c];
        a2 += Agg[(size_t)r * K_DIM + c];
        ++cnt;
    }
    atomicAdd(&g_gs1[cur * K_DIM + c], a1);
    atomicAdd(&g_gs2[cur * K_DIM + c], a2);
    if (c == 0) atomicAdd(&g_gcnt[cur], cnt);
}

// 7) layer-2 on graph means:  hg = (gs1@W2s + gs2@W2n)/cnt + b2
__global__ void k_hg(const float* __restrict__ W2s, const float* __restrict__ W2n,
                     const float* __restrict__ b2) {
    __shared__ float s1[K_DIM], s2[K_DIM];
    int g = blockIdx.x, d = threadIdx.x;
    s1[d] = g_gs1[g * K_DIM + d];
    s2[d] = g_gs2[g * K_DIM + d];
    __syncthreads();
    float acc = 0.0f;
#pragma unroll 4
    for (int k = 0; k < K_DIM; ++k)
        acc += s1[k] * W2s[k * K_DIM + d] + s2[k] * W2n[k * K_DIM + d];
    int cnt = g_gcnt[g];
    float inv = 1.0f / (float)(cnt > 1 ? cnt : 1);
    g_hg[g * K_DIM + d] = acc * inv + b2[d];
}

// 8) classifier: out = [hg|perm] @ Wc + bc
__global__ void k_classifier(const float* __restrict__ perm,
                             const float* __restrict__ Wc,
                             const float* __restrict__ bc,
                             float* __restrict__ out) {
    int t = threadIdx.x;                 // 512
    int g = t >> 3, c = t & 7;
    float acc = bc[c];
#pragma unroll 4
    for (int k = 0; k < K_DIM; ++k)
        acc += g_hg[g * K_DIM + k] * Wc[k * K_CLS + c];
#pragma unroll 4
    for (int k = 0; k < K_DIM; ++k)
        acc += perm[g * K_DIM + k] * Wc[(K_DIM + k) * K_CLS + c];
    out[g * K_CLS + c] = acc;
}

// ---------------------------------------------------------------------------
extern "C" void kernel_launch(void* const* d_in, const int* in_sizes, int n_in,
                              void* d_out, int out_size) {
    const float* h    = (const float*)d_in[0];
    const float* perm = (const float*)d_in[1];
    const int*   src  = (const int*)  d_in[2];
    const int*   dst  = (const int*)  d_in[3];
    const int*   gid  = (const int*)  d_in[4];
    const float* W1s  = (const float*)d_in[5];
    const float* W1n  = (const float*)d_in[6];
    const float* b1   = (const float*)d_in[7];
    const float* W2s  = (const float*)d_in[8];
    const float* W2n  = (const float*)d_in[9];
    const float* b2   = (const float*)d_in[10];
    const float* Wc   = (const float*)d_in[11];
    const float* bc   = (const float*)d_in[12];
    float* out = (float*)d_out;
    (void)in_sizes; (void)n_in; (void)out_size;

    float* meanb;           cudaGetSymbolAddress((void**)&meanb, g_mean);
    float* h1b;             cudaGetSymbolAddress((void**)&h1b,   g_h1);
    __nv_bfloat16* hbb;     cudaGetSymbolAddress((void**)&hbb,   g_hb);
    __nv_bfloat16* h1bb;    cudaGetSymbolAddress((void**)&h1bb,  g_h1b);

    // CSR build + bf16 shadow of h
    k_zero<<<(K_NODES + 255) / 256, 256>>>();
    k_count<<<(K_EDGES + 255) / 256, 256>>>(dst);
    int nquads = K_NODES * K_DIM / 4;
    k_tobf16<<<(nquads + 255) / 256, 256>>>(h, hbb, nquads);
    k_reduce_chunks<<<K_NB, 256>>>();
    k_scan_bsums<<<1, 128>>>();
    k_scan_block<<<K_NB, 256>>>();
    k_fill<<<(K_EDGES + 255) / 256, 256>>>(src, dst);

    int spmmBlocks = (K_NODES * 32 + 255) / 256;
    int gemmBlocks = (K_NODES + 127) / 128;

    // layer 1
    k_spmm_bf16<<<spmmBlocks, 256>>>(hbb, meanb);
    k_gemm_mma<<<gemmBlocks, 256>>>(h, meanb, W1s, W1n, b1, h1b, h1bb, K_NODES);

    // layer 2 on graph means (linearity of mean-pool):
    k_spmm_bf16<<<spmmBlocks, 256>>>(h1bb, meanb);               // agg(h1)
    k_graph_accum2<<<(K_NODES + 63) / 64, 128>>>(h1b, meanb, gid);
    k_hg<<<K_GRAPHS, K_DIM>>>(W2s, W2n, b2);
    k_classifier<<<1, 512>>>(perm, Wc, bc, out);
}

// round 7
// speedup vs baseline: 3.2134x; 1.1264x over previous
#include <cuda_runtime.h>
#include <cuda_bf16.h>
#include <cstdint>
#include <cstring>

// ---------------------------------------------------------------------------
// GraphSAGE (2-layer, mean agg) + graph-mean readout + linear classifier.
// R7: GEMM register-prefetch double buffering; merged prep kernel;
// fused hg+classifier; SpMM 8-wide edge unroll.  Numerics identical to R6.
// ---------------------------------------------------------------------------

#define K_NODES  100000
#define K_EDGES  1600000
#define K_GRAPHS 64
#define K_DIM    128
#define K_CLS    8
#define K_NB     98            // ceil(100000/1024)
#define K_QUADS  (K_NODES * K_DIM / 4)

// scratch (static device memory; no allocations)
__device__ int   g_count [K_NODES];
__device__ int   g_rowptr[K_NODES + 1];
__device__ int   g_cursor[K_NODES];
__device__ int   g_esrc  [K_EDGES];
__device__ int   g_bsum  [128];
__device__ float g_gs1   [K_GRAPHS * K_DIM];
__device__ float g_gs2   [K_GRAPHS * K_DIM];
__device__ int   g_gcnt  [K_GRAPHS];
__device__ float g_mean  [(size_t)K_NODES * K_DIM];
__device__ float g_h1    [(size_t)K_NODES * K_DIM];
__device__ __nv_bfloat16 g_hb  [(size_t)K_NODES * K_DIM];
__device__ __nv_bfloat16 g_h1b [(size_t)K_NODES * K_DIM];

// ---------------------------------------------------------------------------
// 0) prep: zero accumulators + bf16 shadow of h (one launch)
__global__ void k_prep(const float* __restrict__ X, __nv_bfloat16* __restrict__ Y) {
    int i = blockIdx.x * blockDim.x + threadIdx.x;
    if (i < K_NODES)           g_count[i] = 0;
    if (i < K_GRAPHS * K_DIM) { g_gs1[i] = 0.0f; g_gs2[i] = 0.0f; }
    if (i < K_GRAPHS)          g_gcnt[i] = 0;
    if (i < K_QUADS) {
        float4 v = *((const float4*)X + i);
        __nv_bfloat162 a = __floats2bfloat162_rn(v.x, v.y);
        __nv_bfloat162 b = __floats2bfloat162_rn(v.z, v.w);
        uint2 u;
        memcpy(&u.x, &a, 4);
        memcpy(&u.y, &b, 4);
        *((uint2*)Y + i) = u;
    }
}

// 1) histogram of dst
__global__ void k_count(const int* __restrict__ dst) {
    int i = blockIdx.x * blockDim.x + threadIdx.x;
    if (i < K_EDGES) atomicAdd(&g_count[dst[i]], 1);
}

// 2a) per-1024-chunk sums
__global__ void k_reduce_chunks() {
    __shared__ int sm[256];
    int b = blockIdx.x, t = threadIdx.x;
    int base = b * 1024 + t * 4;
    int s = 0;
#pragma unroll
    for (int j = 0; j < 4; ++j) {
        int i = base + j;
        if (i < K_NODES) s += g_count[i];
    }
    sm[t] = s;
    __syncthreads();
    for (int o = 128; o > 0; o >>= 1) {
        if (t < o) sm[t] += sm[t + o];
        __syncthreads();
    }
    if (t == 0) g_bsum[b] = sm[0];
}

// 2b) scan the chunk sums (single block)
__global__ void k_scan_bsums() {
    __shared__ int sm[128];
    int t = threadIdx.x;
    int v = (t < K_NB) ? g_bsum[t] : 0;
    sm[t] = v;
    __syncthreads();
    for (int o = 1; o < 128; o <<= 1) {
        int u = (t >= o) ? sm[t - o] : 0;
        __syncthreads();
        sm[t] += u;
        __syncthreads();
    }
    if (t < K_NB) g_bsum[t] = sm[t] - v;
    if (t == 127) g_rowptr[K_NODES] = sm[127];
}

// 2c) per-chunk exclusive scan -> rowptr, cursor
__global__ void k_scan_block() {
    __shared__ int sm[256];
    int b = blockIdx.x, t = threadIdx.x;
    int base = b * 1024 + t * 4;
    int c[4];
    int s = 0;
#pragma unroll
    for (int j = 0; j < 4; ++j) {
        int i = base + j;
        c[j] = (i < K_NODES) ? g_count[i] : 0;
        s += c[j];
    }
    sm[t] = s;
    __syncthreads();
    for (int o = 1; o < 256; o <<= 1) {
        int u = (t >= o) ? sm[t - o] : 0;
        __syncthreads();
        sm[t] += u;
        __syncthreads();
    }
    int off = g_bsum[b] + sm[t] - s;
#pragma unroll
    for (int j = 0; j < 4; ++j) {
        int i = base + j;
        if (i < K_NODES) {
            g_rowptr[i] = off;
            g_cursor[i] = off;
        }
        off += c[j];
    }
}

// 3) bucket fill: sort edge srcs by dst
__global__ void k_fill(const int* __restrict__ src, const int* __restrict__ dst) {
    int i = blockIdx.x * blockDim.x + threadIdx.x;
    if (i < K_EDGES) {
        int p = atomicAdd(&g_cursor[dst[i]], 1);
        g_esrc[p] = src[i];
    }
}

// ---------------------------------------------------------------------------
// 4) SpMM mean over bf16 rows: one warp per dst row, 8-wide edge unroll
__device__ __forceinline__ void bf16acc(uint2 u, float& ax, float& ay,
                                        float& az, float& aw) {
    __nv_bfloat162 p0, p1;
    memcpy(&p0, &u.x, 4);
    memcpy(&p1, &u.y, 4);
    float2 f0 = __bfloat1622float2(p0);
    float2 f1 = __bfloat1622float2(p1);
    ax += f0.x; ay += f0.y; az += f1.x; aw += f1.y;
}

__global__ void k_spmm_bf16(const __nv_bfloat16* __restrict__ X, float* __restrict__ Y) {
    int w = (blockIdx.x * blockDim.x + threadIdx.x) >> 5;
    int lane = threadIdx.x & 31;
    if (w >= K_NODES) return;
    int e0 = g_rowptr[w], e1 = g_rowptr[w + 1];
    float ax = 0.f, ay = 0.f, az = 0.f, aw = 0.f;
    int e = e0;
    for (; e + 8 <= e1; e += 8) {
        int s[8];
#pragma unroll
        for (int q = 0; q < 8; ++q) s[q] = g_esrc[e + q];
        uint2 u[8];
#pragma unroll
        for (int q = 0; q < 8; ++q)
            u[q] = *((const uint2*)(X + (size_t)s[q] * K_DIM) + lane);
#pragma unroll
        for (int q = 0; q < 8; ++q) bf16acc(u[q], ax, ay, az, aw);
    }
    for (; e + 4 <= e1; e += 4) {
        int s[4];
#pragma unroll
        for (int q = 0; q < 4; ++q) s[q] = g_esrc[e + q];
        uint2 u[4];
#pragma unroll
        for (int q = 0; q < 4; ++q)
            u[q] = *((const uint2*)(X + (size_t)s[q] * K_DIM) + lane);
#pragma unroll
        for (int q = 0; q < 4; ++q) bf16acc(u[q], ax, ay, az, aw);
    }
    for (; e < e1; ++e) {
        int s = g_esrc[e];
        uint2 u = *((const uint2*)(X + (size_t)s * K_DIM) + lane);
        bf16acc(u, ax, ay, az, aw);
    }
    float inv = (e1 > e0) ? 1.0f / (float)(e1 - e0) : 0.0f;
    float4 r;
    r.x = ax * inv; r.y = ay * inv; r.z = az * inv; r.w = aw * inv;
    *((float4*)(Y + (size_t)w * K_DIM) + lane) = r;
}

// ---------------------------------------------------------------------------
// 5) mma.sync tf32 dual GEMM with register-prefetch double buffering.
__device__ __forceinline__ uint32_t f2tf32(float x) {
    uint32_t u;
    asm("cvt.rna.tf32.f32 %0, %1;" : "=r"(u) : "f"(x));
    return u;
}
__device__ __forceinline__ void mma_tf32(float* c, uint32_t a0, uint32_t a1,
                                         uint32_t a2, uint32_t a3,
                                         uint32_t b0, uint32_t b1) {
    asm volatile(
        "mma.sync.aligned.m16n8k8.row.col.f32.tf32.tf32.f32 "
        "{%0,%1,%2,%3}, {%4,%5,%6,%7}, {%8,%9}, {%0,%1,%2,%3};"
        : "+f"(c[0]), "+f"(c[1]), "+f"(c[2]), "+f"(c[3])
        : "r"(a0), "r"(a1), "r"(a2), "r"(a3), "r"(b0), "r"(b1));
}

__global__ __launch_bounds__(256, 2)
void k_gemm_mma(const float* __restrict__ A1, const float* __restrict__ A2,
                const float* __restrict__ W1, const float* __restrict__ W2,
                const float* __restrict__ bias, float* __restrict__ C,
                __nv_bfloat16* __restrict__ Cb, int M) {
    __shared__ __align__(16) uint32_t Xs[32 * 132];   // tf32 bits, [k][row] padded
    __shared__ __align__(16) uint32_t Ws[32 * 128];   // tf32 bits, [k][n]
    int tid = threadIdx.x, wid = tid >> 5, lane = tid & 31;
    int grp = lane >> 2, tig = lane & 3;
    int warpM = wid & 3, warpN = wid >> 2;       // 4 x 2
    int rowBase = blockIdx.x * 128;
    int wr = warpM * 32;
    int wn = warpN * 64;

    int rloc = tid >> 3;             // A stage: row slot
    int kq   = (tid & 7) << 2;       // A stage: k quad
    int wkk  = tid >> 5;             // W stage base
    int wnn  = (tid & 31) << 2;

    float acc[2][8][4];
#pragma unroll
    for (int mt = 0; mt < 2; ++mt)
#pragma unroll
        for (int nt = 0; nt < 8; ++nt)
#pragma unroll
            for (int q = 0; q < 4; ++q) acc[mt][nt][q] = 0.0f;

    float4 ra[4], rw[4];
    // prefetch chunk 0
    {
        const float* A = A1;
        const float* W = W1;
#pragma unroll
        for (int i = 0; i < 4; ++i) {
            int grow = rowBase + rloc + i * 32; if (grow >= M) grow = M - 1;
            ra[i] = *(const float4*)&A[(size_t)grow * K_DIM + kq];
        }
#pragma unroll
        for (int i = 0; i < 4; ++i) {
            int kk = wkk + i * 8;
            rw[i] = *(const float4*)&W[(size_t)kk * K_DIM + wnn];
        }
    }

#pragma unroll 1
    for (int cc = 0; cc < 8; ++cc) {
        __syncthreads();             // prior mma finished reading smem
        // store current regs -> smem (with tf32 cvt)
#pragma unroll
        for (int i = 0; i < 4; ++i) {
            int rr = rloc + i * 32;
            Xs[(kq + 0) * 132 + rr] = f2tf32(ra[i].x);
            Xs[(kq + 1) * 132 + rr] = f2tf32(ra[i].y);
            Xs[(kq + 2) * 132 + rr] = f2tf32(ra[i].z);
            Xs[(kq + 3) * 132 + rr] = f2tf32(ra[i].w);
        }
#pragma unroll
        for (int i = 0; i < 4; ++i) {
            int kk = wkk + i * 8;
            Ws[kk * 128 + wnn + 0] = f2tf32(rw[i].x);
            Ws[kk * 128 + wnn + 1] = f2tf32(rw[i].y);
            Ws[kk * 128 + wnn + 2] = f2tf32(rw[i].z);
            Ws[kk * 128 + wnn + 3] = f2tf32(rw[i].w);
        }
        __syncthreads();
        // prefetch next chunk while mma runs
        if (cc < 7) {
            int nc = cc + 1;
            const float* A = (nc >= 4) ? A2 : A1;
            const float* W = (nc >= 4) ? W2 : W1;
            int k0 = (nc & 3) * 32;
#pragma unroll
            for (int i = 0; i < 4; ++i) {
                int grow = rowBase + rloc + i * 32; if (grow >= M) grow = M - 1;
                ra[i] = *(const float4*)&A[(size_t)grow * K_DIM + k0 + kq];
            }
#pragma unroll
            for (int i = 0; i < 4; ++i) {
                int kk = wkk + i * 8;
                rw[i] = *(const float4*)&W[(size_t)(k0 + kk) * K_DIM + wnn];
            }
        }
        // mma mainloop on smem
#pragma unroll
        for (int ks = 0; ks < 4; ++ks) {
            int kk = ks * 8;
            uint32_t af[2][4];
#pragma unroll
            for (int mt = 0; mt < 2; ++mt) {
                int r = wr + mt * 16 + grp;
                af[mt][0] = Xs[(kk + tig)     * 132 + r];
                af[mt][1] = Xs[(kk + tig)     * 132 + r + 8];
                af[mt][2] = Xs[(kk + tig + 4) * 132 + r];
                af[mt][3] = Xs[(kk + tig + 4) * 132 + r + 8];
            }
#pragma unroll
            for (int nt = 0; nt < 8; ++nt) {
                int n = wn + nt * 8 + grp;
                uint32_t b0 = Ws[(kk + tig)     * 128 + n];
                uint32_t b1 = Ws[(kk + tig + 4) * 128 + n];
                mma_tf32(acc[0][nt], af[0][0], af[0][1], af[0][2], af[0][3], b0, b1);
                mma_tf32(acc[1][nt], af[1][0], af[1][1], af[1][2], af[1][3], b0, b1);
            }
        }
    }

    // epilogue: bias + ReLU; fp32 store + bf16 shadow store
#pragma unroll
    for (int mt = 0; mt < 2; ++mt) {
        int r0g = rowBase + wr + mt * 16 + grp;
        int r1g = r0g + 8;
#pragma unroll
        for (int nt = 0; nt < 8; ++nt) {
            int col = wn + nt * 8 + 2 * tig;
            float2 bv = *(const float2*)&bias[col];
            if (r0g < M) {
                float2 v;
                v.x = fmaxf(acc[mt][nt][0] + bv.x, 0.0f);
                v.y = fmaxf(acc[mt][nt][1] + bv.y, 0.0f);
                *(float2*)&C[(size_t)r0g * K_DIM + col] = v;
                __nv_bfloat162 hb = __floats2bfloat162_rn(v.x, v.y);
                *(__nv_bfloat162*)&Cb[(size_t)r0g * K_DIM + col] = hb;
            }
            if (r1g < M) {
                float2 v;
                v.x = fmaxf(acc[mt][nt][2] + bv.x, 0.0f);
                v.y = fmaxf(acc[mt][nt][3] + bv.y, 0.0f);
                *(float2*)&C[(size_t)r1g * K_DIM + col] = v;
                __nv_bfloat162 hb = __floats2bfloat162_rn(v.x, v.y);
                *(__nv_bfloat162*)&Cb[(size_t)r1g * K_DIM + col] = hb;
            }
        }
    }
}

// ---------------------------------------------------------------------------
// 6) fused per-graph sums of h1 AND agg(h1): segmented register accumulation
__global__ void k_graph_accum2(const float* __restrict__ H,
                               const float* __restrict__ Agg,
                               const int* __restrict__ gid) {
    int c = threadIdx.x;                 // 128 threads = one dim each
    int rs = blockIdx.x * 64;
    if (rs >= K_NODES) return;
    int re = rs + 64;
    if (re > K_NODES) re = K_NODES;
    int cur = gid[rs];
    float a1 = 0.0f, a2 = 0.0f;
    int cnt = 0;
    for (int r = rs; r < re; ++r) {
        int g = gid[r];
        if (g != cur) {
            atomicAdd(&g_gs1[cur * K_DIM + c], a1);
            atomicAdd(&g_gs2[cur * K_DIM + c], a2);
            if (c == 0) atomicAdd(&g_gcnt[cur], cnt);
            a1 = 0.0f; a2 = 0.0f; cnt = 0; cur = g;
        }
        a1 += H  [(size_t)r * K_DIM + c];
        a2 += Agg[(size_t)r * K_DIM + c];
        ++cnt;
    }
    atomicAdd(&g_gs1[cur * K_DIM + c], a1);
    atomicAdd(&g_gs2[cur * K_DIM + c], a2);
    if (c == 0) atomicAdd(&g_gcnt[cur], cnt);
}

// 7) fused: hg = (gs1@W2s + gs2@W2n)/cnt + b2 ; out = [hg|perm]@Wc + bc
__global__ void k_hgcls(const float* __restrict__ W2s, const float* __restrict__ W2n,
                        const float* __restrict__ b2,
                        const float* __restrict__ perm,
                        const float* __restrict__ Wc,
                        const float* __restrict__ bc,
                        float* __restrict__ out) {
    __shared__ float s1[K_DIM], s2[K_DIM], hgs[K_DIM];
    __shared__ float red[K_CLS];
    int g = blockIdx.x, d = threadIdx.x;
    s1[d] = g_gs1[g * K_DIM + d];
    s2[d] = g_gs2[g * K_DIM + d];
    if (d < K_CLS) red[d] = bc[d];
    __syncthreads();
    float acc = 0.0f;
#pragma unroll 4
    for (int k = 0; k < K_DIM; ++k)
        acc += s1[k] * W2s[k * K_DIM + d] + s2[k] * W2n[k * K_DIM + d];
    int cnt = g_gcnt[g];
    float inv = 1.0f / (float)(cnt > 1 ? cnt : 1);
    hgs[d] = acc * inv + b2[d];
    __syncthreads();
    // classifier: 64 threads, thread = (class c, 32-k segment)
    if (d < 64) {
        int c = d & 7, seg = d >> 3;
        int k0 = seg * 32;
        float p = 0.0f;
#pragma unroll 4
        for (int k = k0; k < k0 + 32; ++k) {
            float val = (k < K_DIM) ? hgs[k] : perm[g * K_DIM + (k - K_DIM)];
            p += val * Wc[k * K_CLS + c];
        }
        atomicAdd(&red[c], p);
    }
    __syncthreads();
    if (d < K_CLS) out[g * K_CLS + d] = red[d];
}

// ---------------------------------------------------------------------------
extern "C" void kernel_launch(void* const* d_in, const int* in_sizes, int n_in,
                              void* d_out, int out_size) {
    const float* h    = (const float*)d_in[0];
    const float* perm = (const float*)d_in[1];
    const int*   src  = (const int*)  d_in[2];
    const int*   dst  = (const int*)  d_in[3];
    const int*   gid  = (const int*)  d_in[4];
    const float* W1s  = (const float*)d_in[5];
    const float* W1n  = (const float*)d_in[6];
    const float* b1   = (const float*)d_in[7];
    const float* W2s  = (const float*)d_in[8];
    const float* W2n  = (const float*)d_in[9];
    const float* b2   = (const float*)d_in[10];
    const float* Wc   = (const float*)d_in[11];
    const float* bc   = (const float*)d_in[12];
    float* out = (float*)d_out;
    (void)in_sizes; (void)n_in; (void)out_size;

    float* meanb;           cudaGetSymbolAddress((void**)&meanb, g_mean);
    float* h1b;             cudaGetSymbolAddress((void**)&h1b,   g_h1);
    __nv_bfloat16* hbb;     cudaGetSymbolAddress((void**)&hbb,   g_hb);
    __nv_bfloat16* h1bb;    cudaGetSymbolAddress((void**)&h1bb,  g_h1b);

    // CSR build (+ bf16 shadow of h inside prep)
    k_prep<<<(K_QUADS + 255) / 256, 256>>>(h, hbb);
    k_count<<<(K_EDGES + 255) / 256, 256>>>(dst);
    k_reduce_chunks<<<K_NB, 256>>>();
    k_scan_bsums<<<1, 128>>>();
    k_scan_block<<<K_NB, 256>>>();
    k_fill<<<(K_EDGES + 255) / 256, 256>>>(src, dst);

    int spmmBlocks = (K_NODES * 32 + 255) / 256;
    int gemmBlocks = (K_NODES + 127) / 128;

    // layer 1
    k_spmm_bf16<<<spmmBlocks, 256>>>(hbb, meanb);
    k_gemm_mma<<<gemmBlocks, 256>>>(h, meanb, W1s, W1n, b1, h1b, h1bb, K_NODES);

    // layer 2 on graph means (linearity of mean-pool):
    k_spmm_bf16<<<spmmBlocks, 256>>>(h1bb, meanb);               // agg(h1)
    k_graph_accum2<<<(K_NODES + 63) / 64, 128>>>(h1b, meanb, gid);
    k_hgcls<<<K_GRAPHS, K_DIM>>>(W2s, W2n, b2, perm, Wc, bc, out);
}